// round 3
// baseline (speedup 1.0000x reference)
#include <cuda_runtime.h>

// TinyFormerEncoder: B=65536, S=16, D=32, FFN=64, fp32.
// Round 3: 2 rows per thread to halve shared-memory (L1) traffic, which ncu
// showed as the bottleneck (L1=94%, fma=39%).
// 64 threads/block = 8 batches/block (each thread owns rows s and s+8 of one
// batch); 8192 blocks. Static smem = 48KB: K/V 32KB + 16KB phased weights.
// All math in packed fp32x2 FMA.

typedef unsigned long long u64;

__device__ __forceinline__ u64 pack2(float lo, float hi) {
    u64 r; asm("mov.b64 %0, {%1, %2};" : "=l"(r) : "f"(lo), "f"(hi)); return r;
}
__device__ __forceinline__ void unpack2(u64 v, float& lo, float& hi) {
    asm("mov.b64 {%0, %1}, %2;" : "=f"(lo), "=f"(hi) : "l"(v));
}
__device__ __forceinline__ u64 dup2(float x) { return pack2(x, x); }
__device__ __forceinline__ void ffma2(u64& d, u64 a, u64 b) {
    asm("fma.rn.f32x2 %0, %1, %2, %3;" : "=l"(d) : "l"(a), "l"(b), "l"(d));
}
__device__ __forceinline__ void fadd2(u64& d, u64 a, u64 b) {
    asm("add.rn.f32x2 %0, %1, %2;" : "=l"(d) : "l"(a), "l"(b));
}
__device__ __forceinline__ u64 ldg2(const float* p) {
    float2 t = __ldg((const float2*)p); return pack2(t.x, t.y);
}

static constexpr int THREADS = 64;
static constexpr int BPB     = 8;   // batches per block

// One 32-float weight row (8x16B), FMA'd into two 16-u64 accumulators.
__device__ __forceinline__ void wrow2(const float* __restrict__ Wrow,
                                      u64 a, u64 b, u64* accA, u64* accB) {
    const ulonglong2* w2 = (const ulonglong2*)Wrow;
    #pragma unroll
    for (int p = 0; p < 8; p++) {
        ulonglong2 w = w2[p];
        ffma2(accA[2*p],   a, w.x); ffma2(accA[2*p+1], a, w.y);
        ffma2(accB[2*p],   b, w.x); ffma2(accB[2*p+1], b, w.y);
    }
}
// 16-float segment of a weight row (4x16B) into two 8-u64 accumulators.
__device__ __forceinline__ void wseg2(const float* __restrict__ Wseg,
                                      u64 a, u64 b, u64* accA, u64* accB) {
    const ulonglong2* w2 = (const ulonglong2*)Wseg;
    #pragma unroll
    for (int p = 0; p < 4; p++) {
        ulonglong2 w = w2[p];
        ffma2(accA[2*p],   a, w.x); ffma2(accA[2*p+1], a, w.y);
        ffma2(accB[2*p],   b, w.x); ffma2(accB[2*p+1], b, w.y);
    }
}

// acc{A,B}[16] = bias + x{A,B}(32 scalars) @ W[32][32]; weight rows read ONCE.
__device__ __forceinline__ void proj2(const float* __restrict__ W,
                                      const float* __restrict__ bias,
                                      const float* xA, const float* xB,
                                      u64* accA, u64* accB) {
    #pragma unroll
    for (int jp = 0; jp < 16; jp++) { accA[jp] = ldg2(bias + 2*jp); accB[jp] = accA[jp]; }
    #pragma unroll
    for (int d = 0; d < 32; d++)
        wrow2(W + d * 32, dup2(xA[d]), dup2(xB[d]), accA, accB);
}

__device__ __forceinline__ void cp4(float* dst, const float* __restrict__ src, int n) {
    for (int i = threadIdx.x; i < (n >> 2); i += THREADS)
        ((float4*)dst)[i] = ((const float4*)src)[i];
}

__global__ void __launch_bounds__(THREADS, 4)
tinyformer_kernel(const float* __restrict__ x,
                  const float* __restrict__ Wq, const float* __restrict__ bq,
                  const float* __restrict__ Wk, const float* __restrict__ bk,
                  const float* __restrict__ Wv, const float* __restrict__ bv,
                  const float* __restrict__ Wo, const float* __restrict__ bo,
                  const float* __restrict__ W1, const float* __restrict__ b1,
                  const float* __restrict__ W2, const float* __restrict__ b2,
                  float* __restrict__ out)
{
    // K rows [0:4096], V rows [4096:8192]; 128 rows x 32 floats, 16B blocks
    // rotated by (s+bl)&7 for bank spread.
    __shared__ __align__(16) float skv[8192];
    // Phase buffer: P1 Wq|Wk|Wv (3x1024), P2 Wo (1024), P3 W1(2048)|W2(2048).
    __shared__ __align__(16) float swb[4096];

    const int tid = threadIdx.x;
    const int bl  = tid >> 3;         // batch-in-block 0..7
    const int s0  = tid & 7;          // rows s0 and s0+8
    const size_t b = (size_t)blockIdx.x * BPB + bl;
    const size_t offA = (b * 16 + s0) * 32;
    const size_t offB = (b * 16 + s0 + 8) * 32;

    // ---- phase 1 weights ----
    cp4(swb + 0,    Wq, 1024);
    cp4(swb + 1024, Wk, 1024);
    cp4(swb + 2048, Wv, 1024);
    __syncthreads();

    // ---- load both x rows ----
    float xA[32], xB[32];
    {
        const float4* pa = (const float4*)(x + offA);
        const float4* pb = (const float4*)(x + offB);
        #pragma unroll
        for (int i = 0; i < 8; i++) {
            float4 t = pa[i];
            xA[4*i+0]=t.x; xA[4*i+1]=t.y; xA[4*i+2]=t.z; xA[4*i+3]=t.w;
            float4 u = pb[i];
            xB[4*i+0]=u.x; xB[4*i+1]=u.y; xB[4*i+2]=u.z; xB[4*i+3]=u.w;
        }
    }

    // ---- K,V -> smem (swizzled); Q -> regs ----
    {
        u64 aA[16], aB[16];
        proj2(swb + 1024, bk, xA, xB, aA, aB);
        {   // store K rows s0, s0+8
            ulonglong2* base = (ulonglong2*)skv;
            int rA = bl*16 + s0,     rotA = (s0 + bl) & 7;
            int rB = bl*16 + s0 + 8, rotB = (s0 + 8 + bl) & 7;
            #pragma unroll
            for (int p = 0; p < 8; p++) {
                base[rA*8 + ((p+rotA)&7)] = make_ulonglong2(aA[2*p], aA[2*p+1]);
                base[rB*8 + ((p+rotB)&7)] = make_ulonglong2(aB[2*p], aB[2*p+1]);
            }
        }
        proj2(swb + 2048, bv, xA, xB, aA, aB);
        {   // store V rows
            ulonglong2* base = (ulonglong2*)(skv + 4096);
            int rA = bl*16 + s0,     rotA = (s0 + bl) & 7;
            int rB = bl*16 + s0 + 8, rotB = (s0 + 8 + bl) & 7;
            #pragma unroll
            for (int p = 0; p < 8; p++) {
                base[rA*8 + ((p+rotA)&7)] = make_ulonglong2(aA[2*p], aA[2*p+1]);
                base[rB*8 + ((p+rotB)&7)] = make_ulonglong2(aB[2*p], aB[2*p+1]);
            }
        }
    }
    u64 qA[16], qB[16];
    proj2(swb + 0, bq, xA, xB, qA, qB);
    __syncthreads();                 // K/V visible; phase-1 reads done

    // phase 2 (Wo) issued before attention math
    cp4(swb + 0, Wo, 1024);

    // ---- scores: both rows share this batch's K (one LDS serves both) ----
    float scA[16], scB[16];
    {
        const ulonglong2* kb = (const ulonglong2*)skv + bl * 16 * 8;
        #pragma unroll
        for (int t = 0; t < 16; t++) {
            int rot = (t + bl) & 7;
            const ulonglong2* kr = kb + t * 8;
            u64 e0=0ull, e1=0ull, f0=0ull, f1=0ull;
            #pragma unroll
            for (int p = 0; p < 8; p++) {
                ulonglong2 w = kr[(p+rot)&7];
                ffma2(e0, qA[2*p],   w.x); ffma2(e1, qA[2*p+1], w.y);
                ffma2(f0, qB[2*p],   w.x); ffma2(f1, qB[2*p+1], w.y);
            }
            float a0,a1,a2,a3; unpack2(e0,a0,a1); unpack2(e1,a2,a3);
            scA[t] = (a0+a1+a2+a3) * 0.17677669529663687f;
            unpack2(f0,a0,a1); unpack2(f1,a2,a3);
            scB[t] = (a0+a1+a2+a3) * 0.17677669529663687f;
        }
    }

    // ---- softmax (in-thread, 16-wide, per row) ----
    #pragma unroll
    for (int r = 0; r < 2; r++) {
        float* sc = r ? scB : scA;
        float m = sc[0];
        #pragma unroll
        for (int t = 1; t < 16; t++) m = fmaxf(m, sc[t]);
        float sum = 0.f;
        #pragma unroll
        for (int t = 0; t < 16; t++) { sc[t] = __expf(sc[t] - m); sum += sc[t]; }
        float inv = __fdividef(1.f, sum);
        #pragma unroll
        for (int t = 0; t < 16; t++) sc[t] *= inv;
    }

    // ---- context: shared V reads serve both rows ----
    u64 cA[16], cB[16];
    #pragma unroll
    for (int jp = 0; jp < 16; jp++) { cA[jp]=0ull; cB[jp]=0ull; }
    {
        const ulonglong2* vb = (const ulonglong2*)(skv + 4096) + bl * 16 * 8;
        #pragma unroll
        for (int t = 0; t < 16; t++) {
            int rot = (t + bl) & 7;
            const ulonglong2* vr = vb + t * 8;
            u64 av = dup2(scA[t]), bv2 = dup2(scB[t]);
            #pragma unroll
            for (int p = 0; p < 8; p++) {
                ulonglong2 w = vr[(p+rot)&7];
                ffma2(cA[2*p],   av,  w.x); ffma2(cA[2*p+1], av,  w.y);
                ffma2(cB[2*p],   bv2, w.x); ffma2(cB[2*p+1], bv2, w.y);
            }
        }
    }
    __syncthreads();                 // Wo visible

    // ---- y = x + ctx @ Wo + bo (x reloaded from gmem; DRAM is idle) ----
    u64 yA[16], yB[16];
    #pragma unroll
    for (int jp = 0; jp < 16; jp++) { yA[jp] = ldg2(bo + 2*jp); yB[jp] = yA[jp]; }
    {
        const ulonglong2* pa = (const ulonglong2*)(x + offA);
        const ulonglong2* pb = (const ulonglong2*)(x + offB);
        #pragma unroll
        for (int p = 0; p < 8; p++) {
            ulonglong2 ta = pa[p], tb = pb[p];
            fadd2(yA[2*p], yA[2*p], ta.x); fadd2(yA[2*p+1], yA[2*p+1], ta.y);
            fadd2(yB[2*p], yB[2*p], tb.x); fadd2(yB[2*p+1], yB[2*p+1], tb.y);
        }
    }
    #pragma unroll
    for (int d2 = 0; d2 < 16; d2++) {
        float a0,a1,b0,b1;
        unpack2(cA[d2], a0, a1); unpack2(cB[d2], b0, b1);
        wrow2(swb + (2*d2)   * 32, dup2(a0), dup2(b0), yA, yB);
        wrow2(swb + (2*d2+1) * 32, dup2(a1), dup2(b1), yA, yB);
    }
    __syncthreads();                 // Wo reads done

    // ---- phase 3: W1 + W2 fully resident ----
    cp4(swb + 0,    W1, 2048);
    cp4(swb + 2048, W2, 2048);
    __syncthreads();

    // ---- z = y + b2 + relu(y@W1+b1)@W2, hidden in 4 chunks of 16 ----
    u64 zA[16], zB[16];
    #pragma unroll
    for (int jp = 0; jp < 16; jp++) {
        zA[jp] = yA[jp]; fadd2(zA[jp], zA[jp], ldg2(b2 + 2*jp));
        zB[jp] = yB[jp]; fadd2(zB[jp], zB[jp], ldg2(b2 + 2*jp));
    }
    #pragma unroll
    for (int c = 0; c < 4; c++) {
        u64 hA[8], hB[8];
        #pragma unroll
        for (int j = 0; j < 8; j++) { hA[j] = ldg2(b1 + 16*c + 2*j); hB[j] = hA[j]; }
        #pragma unroll
        for (int d2 = 0; d2 < 16; d2++) {
            float a0,a1,b0,b1;
            unpack2(yA[d2], a0, a1); unpack2(yB[d2], b0, b1);
            wseg2(swb + (2*d2)   * 64 + 16*c, dup2(a0), dup2(b0), hA, hB);
            wseg2(swb + (2*d2+1) * 64 + 16*c, dup2(a1), dup2(b1), hA, hB);
        }
        #pragma unroll
        for (int f2 = 0; f2 < 8; f2++) {
            float p0,p1,q0,q1;
            unpack2(hA[f2], p0, p1); unpack2(hB[f2], q0, q1);
            p0 = fmaxf(p0, 0.f); p1 = fmaxf(p1, 0.f);
            q0 = fmaxf(q0, 0.f); q1 = fmaxf(q1, 0.f);
            int hrow = 16*c + 2*f2;
            wrow2(swb + 2048 + hrow     * 32, dup2(p0), dup2(q0), zA, zB);
            wrow2(swb + 2048 + (hrow+1) * 32, dup2(p1), dup2(q1), zA, zB);
        }
    }

    // ---- store both rows ----
    {
        ulonglong2* oa = (ulonglong2*)(out + offA);
        ulonglong2* ob = (ulonglong2*)(out + offB);
        #pragma unroll
        for (int p = 0; p < 8; p++) {
            oa[p] = make_ulonglong2(zA[2*p], zA[2*p+1]);
            ob[p] = make_ulonglong2(zB[2*p], zB[2*p+1]);
        }
    }
}

extern "C" void kernel_launch(void* const* d_in, const int* in_sizes, int n_in,
                              void* d_out, int out_size)
{
    (void)in_sizes; (void)n_in; (void)out_size;
    const float* x  = (const float*)d_in[0];
    const float* Wq = (const float*)d_in[1];
    const float* bq = (const float*)d_in[2];
    const float* Wk = (const float*)d_in[3];
    const float* bk = (const float*)d_in[4];
    const float* Wv = (const float*)d_in[5];
    const float* bv = (const float*)d_in[6];
    const float* Wo = (const float*)d_in[7];
    const float* bo = (const float*)d_in[8];
    const float* W1 = (const float*)d_in[9];
    const float* b1 = (const float*)d_in[10];
    const float* W2 = (const float*)d_in[11];
    const float* b2 = (const float*)d_in[12];
    float* out = (float*)d_out;

    tinyformer_kernel<<<65536 / BPB, THREADS>>>(
        x, Wq, bq, Wk, bk, Wv, bv, Wo, bo, W1, b1, W2, b2, out);
}